// round 16
// baseline (speedup 1.0000x reference)
#include <cuda_runtime.h>
#include <cuda_bf16.h>

// SNN dense (TTFS) — B=64, IN=1024 (+1 bias row), OUT=1024.
//   K1: stable rank-count sort, 4-way split of compare range (R10 proven).
//   K2: STATIC one-item-per-CTA scan (512 CTAs, MBLK=128, 4 neurons/lane,
//       LDG.128 per k); packed f32x2 accumulators; division-free validity
//       (R15 proven); no atomics, no stealing, no peel.

#define BATCH 64
#define IN_SZ 1024
#define KTOT 1025          // IN_SZ + bias
#define OUT_SZ 1024
#define MAXT 100000.0f
#define BIASV 1.0f

#define NW 16              // warps (K-chunks) per item
#define CHUNK ((KTOT + NW - 1) / NW)   // 65
#define MBLK 128           // outputs per item (4 per lane)
#define NITEMS (BATCH * (OUT_SZ / MBLK))   // 512
#define GRID_SCAN NITEMS   // one CTA per item, fully static

#define SORT_ELEMS 64
#define SORT_PARTS 4
#define SORT_BLOCK (SORT_ELEMS * SORT_PARTS)   // 256
#define J2TOT ((KTOT + 1) / 2)                 // 513 ull2 chunks

typedef unsigned long long ull;

// packed f32x2 helpers (sm_103a FFMA2/FADD2 — only reachable via PTX)
__device__ __forceinline__ ull f2_add(ull a, ull b) {
    ull r; asm("add.rn.f32x2 %0,%1,%2;" : "=l"(r) : "l"(a), "l"(b)); return r;
}
__device__ __forceinline__ ull f2_fma(ull a, ull b, ull c) {
    ull r; asm("fma.rn.f32x2 %0,%1,%2,%3;" : "=l"(r) : "l"(a), "l"(b), "l"(c)); return r;
}
__device__ __forceinline__ ull f2_bcast(float x) {
    ull r; asm("mov.b64 %0,{%1,%1};" : "=l"(r) : "f"(x)); return r;
}
__device__ __forceinline__ void f2_unpack(float& lo, float& hi, ull v) {
    asm("mov.b64 {%0,%1},%2;" : "=f"(lo), "=f"(hi) : "l"(v));
}

// Scratch (device globals; no allocation allowed)
__device__ int2 g_pack[BATCH][KTOT + 1];  // {float bits of x, W byte offset}

// ---------------------------------------------------------------------------
// Kernel 1: stable counting sort via packed u64 keys, 4-way range split.
// key = (float_bits << 32) | index — positive floats order as uints; index
// tie-break = exact jnp.argsort stability.
// ---------------------------------------------------------------------------
__global__ void __launch_bounds__(SORT_BLOCK) snn_sort_kernel(const float* __restrict__ X) {
    const int b = blockIdx.y;
    __shared__ ull sk[KTOT + 1];
    __shared__ int pr[SORT_ELEMS][SORT_PARTS];

    for (int j = threadIdx.x; j < KTOT; j += SORT_BLOCK) {
        float v = (j < IN_SZ) ? X[b * IN_SZ + j] : BIASV;
        sk[j] = ((ull)__float_as_uint(v) << 32) | (unsigned)j;
    }
    if (threadIdx.x == 0) {
        sk[KTOT] = ~0ull;
        int2 s; s.x = __float_as_int(MAXT); s.y = 0;
        if (blockIdx.x == 0) g_pack[b][KTOT] = s;      // next_x sentinel
    }
    __syncthreads();

    const int li   = threadIdx.x & (SORT_ELEMS - 1);
    const int part = threadIdx.x >> 6;
    const int i    = blockIdx.x * SORT_ELEMS + li;
    const bool valid = (i < KTOT);

    const ull ki = valid ? sk[i] : ~0ull;
    const int lo = (J2TOT * part) / SORT_PARTS;
    const int hi = (J2TOT * (part + 1)) / SORT_PARTS;

    int r = 0;
    const ulonglong2* sk2 = reinterpret_cast<const ulonglong2*>(sk);
    #pragma unroll 4
    for (int j2 = lo; j2 < hi; ++j2) {
        ulonglong2 v = sk2[j2];
        r += (v.x < ki);
        r += (v.y < ki);
    }
    pr[li][part] = r;
    __syncthreads();

    if (part == 0 && valid) {
        int rank = pr[li][0] + pr[li][1] + pr[li][2] + pr[li][3];
        int2 p;
        p.x = (int)(ki >> 32);
        p.y = ((int)(ki & 0xFFFFFFFFu)) * (OUT_SZ * 4);
        g_pack[b][rank] = p;
    }
}

// ---------------------------------------------------------------------------
// Kernel 2: static scan, one item per CTA. grid = 512, block = 512.
// Item = (b, m-block of 128). Warp w owns k in [w*CHUNK, ...); lane L owns
// outputs mbase + 4L .. 4L+3 (one LDG.128 per k). cw starts at -1
// (threshold folded). Validity: cand = ct/cw in [x,nx] with cw>0  <=>
// cw>0 & ct-x*cw>=0 & nx*cw-ct>=0 (no division; divide only when valid).
// ---------------------------------------------------------------------------
__global__ void __launch_bounds__(512, 4) snn_scan_kernel(const float* __restrict__ W,
                                                          float* __restrict__ out) {
    __shared__ int2       sp[KTOT + 1];
    __shared__ ulonglong2 pw[NW][32];     // packed chunk sums of w (2 pairs)
    __shared__ ulonglong2 pt[NW][32];     // packed chunk sums of w*x
    __shared__ float      pm[NW][MBLK];   // per-chunk minima

    const int item  = blockIdx.x;
    const int b     = item >> 3;               // item / (OUT_SZ/MBLK)
    const int mbase = (item & 7) * MBLK;

    const int w    = threadIdx.x >> 5;
    const int lane = threadIdx.x & 31;
    const int k0 = w * CHUNK;
    const int k1 = (k0 + CHUNK < KTOT) ? (k0 + CHUNK) : KTOT;

    for (int j = threadIdx.x; j < KTOT + 1; j += blockDim.x)
        sp[j] = g_pack[b][j];
    __syncthreads();

    const char* Wb = (const char*)W + (size_t)(mbase + 4 * lane) * 4;

    // ---- pass 1: packed chunk partial sums (warp 15's unused) ----
    if (w < NW - 1) {
        ull sa = 0ull, ta = 0ull, sb = 0ull, tb = 0ull;
        #pragma unroll 4
        for (int k = k0; k < k1; ++k) {
            const int2 p = sp[k];
            const ulonglong2 w2 = *reinterpret_cast<const ulonglong2*>(Wb + p.y);
            const ull x2 = f2_bcast(__int_as_float(p.x));
            sa = f2_add(sa, w2.x);
            ta = f2_fma(w2.x, x2, ta);
            sb = f2_add(sb, w2.y);
            tb = f2_fma(w2.y, x2, tb);
        }
        ulonglong2 sv; sv.x = sa; sv.y = sb;
        ulonglong2 tv; tv.x = ta; tv.y = tb;
        pw[w][lane] = sv;
        pt[w][lane] = tv;
    }
    __syncthreads();

    // ---- exclusive prefix (threshold folded: start at -1) ----
    ull cwa = 0xBF800000BF800000ull, cta = 0ull;   // neurons 0,1
    ull cwb = 0xBF800000BF800000ull, ctb = 0ull;   // neurons 2,3
    for (int c = 0; c < w; ++c) {
        const ulonglong2 a = pw[c][lane];
        const ulonglong2 d = pt[c][lane];
        cwa = f2_add(cwa, a.x); cta = f2_add(cta, d.x);
        cwb = f2_add(cwb, a.y); ctb = f2_add(ctb, d.y);
    }

    // ---- pass 2: scan chunk, division-free validity ----
    float best0 = MAXT, best1 = MAXT, best2 = MAXT, best3 = MAXT;
    int2 pc = sp[k0];
    #pragma unroll 4
    for (int k = k0; k < k1; ++k) {
        const float x  = __int_as_float(pc.x);
        const int  off = pc.y;
        pc = sp[k + 1];
        const float nx = __int_as_float(pc.x);   // sentinel gives MAXT at k=KTOT-1
        const ulonglong2 w2 = *reinterpret_cast<const ulonglong2*>(Wb + off);
        const ull x2 = f2_bcast(x);

        cwa = f2_add(cwa, w2.x); cta = f2_fma(w2.x, x2, cta);
        cwb = f2_add(cwb, w2.y); ctb = f2_fma(w2.y, x2, ctb);
        float cw0, cw1, cw2, cw3, ct0, ct1, ct2, ct3;
        f2_unpack(cw0, cw1, cwa); f2_unpack(ct0, ct1, cta);
        f2_unpack(cw2, cw3, cwb); f2_unpack(ct2, ct3, ctb);

        const float a0 = fmaf(-x, cw0, ct0), b0 = fmaf(nx, cw0, -ct0);
        const float a1 = fmaf(-x, cw1, ct1), b1 = fmaf(nx, cw1, -ct1);
        const float a2 = fmaf(-x, cw2, ct2), b2 = fmaf(nx, cw2, -ct2);
        const float a3 = fmaf(-x, cw3, ct3), b3 = fmaf(nx, cw3, -ct3);
        const bool v0 = (cw0 > 0.f) & (a0 >= 0.f) & (b0 >= 0.f);
        const bool v1 = (cw1 > 0.f) & (a1 >= 0.f) & (b1 >= 0.f);
        const bool v2 = (cw2 > 0.f) & (a2 >= 0.f) & (b2 >= 0.f);
        const bool v3 = (cw3 > 0.f) & (a3 >= 0.f) & (b3 >= 0.f);

        if (__any_sync(0xFFFFFFFFu, v0 | v1 | v2 | v3)) {   // rare
            if (v0) best0 = fminf(best0, __fdividef(ct0, cw0));
            if (v1) best1 = fminf(best1, __fdividef(ct1, cw1));
            if (v2) best2 = fminf(best2, __fdividef(ct2, cw2));
            if (v3) best3 = fminf(best3, __fdividef(ct3, cw3));
        }
    }
    pm[w][4 * lane]     = best0;
    pm[w][4 * lane + 1] = best1;
    pm[w][4 * lane + 2] = best2;
    pm[w][4 * lane + 3] = best3;
    __syncthreads();

    // ---- final min across chunks: threads 0..127, one output each ----
    if (threadIdx.x < MBLK) {
        float bb = MAXT;
        #pragma unroll
        for (int c = 0; c < NW; ++c)
            bb = fminf(bb, pm[c][threadIdx.x]);
        out[b * OUT_SZ + mbase + threadIdx.x] = bb;
    }
}

// ---------------------------------------------------------------------------
extern "C" void kernel_launch(void* const* d_in, const int* in_sizes, int n_in,
                              void* d_out, int out_size) {
    const float* X = (const float*)d_in[0];
    const float* W = (const float*)d_in[1];
    if (n_in >= 2 && in_sizes[0] != BATCH * IN_SZ && in_sizes[1] == BATCH * IN_SZ) {
        X = (const float*)d_in[1];
        W = (const float*)d_in[0];
    }
    float* out = (float*)d_out;

    dim3 gs((KTOT + SORT_ELEMS - 1) / SORT_ELEMS, BATCH);   // (17, 64)
    snn_sort_kernel<<<gs, SORT_BLOCK>>>(X);

    snn_scan_kernel<<<GRID_SCAN, 512>>>(W, out);
}